// round 14
// baseline (speedup 1.0000x reference)
#include <cuda_runtime.h>
#include <cstdint>

#define NSTEPS 10
#define NB     512
#define NT     256
#define NBAR   13
#define NSUB   16
#define NELEMS 262144
#define MASK52 ((1ull << 52) - 1ull)
#define CNT1   (1ull << 52)
#define WSTRIDE 76
#define MSTRIDE 36

// ---------------- device scratch ----------------
__device__ float g_C[16 * 2048];
__device__ float g_pre1[4096 * 32];
__device__ float g_err32[32];
__device__ float g_fgabs[128];
struct SSlot { unsigned long long v; unsigned long long pad[31]; };  // 256B
__device__ SSlot g_sync[NBAR * NSUB];   // zero-init; block 0 re-zeroes at run end

struct Keys { unsigned k0[NSTEPS]; unsigned k1[NSTEPS]; };

// ---------------- threefry2x32 ----------------
// host version (key derivation only)
#define TF_ROT_H(x, r) (((x) << (r)) | ((x) >> (32 - (r))))
static inline void tf2x32_host(unsigned k0, unsigned k1, unsigned x0, unsigned x1,
                               unsigned* o0, unsigned* o1) {
  unsigned ks0 = k0, ks1 = k1, ks2 = k0 ^ k1 ^ 0x1BD11BDAu;
  x0 += ks0; x1 += ks1;
#define TF_R4(a,b,c,d) \
  x0 += x1; x1 = TF_ROT_H(x1,a); x1 ^= x0; \
  x0 += x1; x1 = TF_ROT_H(x1,b); x1 ^= x0; \
  x0 += x1; x1 = TF_ROT_H(x1,c); x1 ^= x0; \
  x0 += x1; x1 = TF_ROT_H(x1,d); x1 ^= x0;
  TF_R4(13,15,26,6)  x0 += ks1; x1 += ks2 + 1u;
  TF_R4(17,29,16,24) x0 += ks2; x1 += ks0 + 2u;
  TF_R4(13,15,26,6)  x0 += ks0; x1 += ks1 + 3u;
  TF_R4(17,29,16,24) x0 += ks1; x1 += ks2 + 4u;
  TF_R4(13,15,26,6)  x0 += ks2; x1 += ks0 + 5u;
#undef TF_R4
  *o0 = x0; *o1 = x1;
}

// device version: forced single-instruction SHF rotates
__device__ __forceinline__ unsigned rotl(unsigned x, int r) {
  return __funnelshift_l(x, x, r);
}
__device__ __forceinline__ unsigned tfxor(unsigned k0, unsigned k1, unsigned e) {
  unsigned ks2 = k0 ^ k1 ^ 0x1BD11BDAu;
  unsigned x0 = k0;        // 0 + ks0
  unsigned x1 = e + k1;    // e + ks1
#define TF_R4D(a,b,c,d) \
  x0 += x1; x1 = rotl(x1,a); x1 ^= x0; \
  x0 += x1; x1 = rotl(x1,b); x1 ^= x0; \
  x0 += x1; x1 = rotl(x1,c); x1 ^= x0; \
  x0 += x1; x1 = rotl(x1,d); x1 ^= x0;
  TF_R4D(13,15,26,6)  x0 += k1;  x1 += ks2 + 1u;
  TF_R4D(17,29,16,24) x0 += ks2; x1 += k0 + 2u;
  TF_R4D(13,15,26,6)  x0 += k0;  x1 += k1 + 3u;
  TF_R4D(17,29,16,24) x0 += k1;  x1 += ks2 + 4u;
  TF_R4D(13,15,26,6)  x0 += ks2; x1 += k0 + 5u;
#undef TF_R4D
  return x0 ^ x1;
}

__device__ __forceinline__ float bits_to_normal(unsigned bits) {
  float f = __uint_as_float((bits >> 9) | 0x3f800000u) - 1.0f;
  const float lo = __uint_as_float(0xBF7FFFFFu);
  float u = fmaxf(lo, f * 2.0f + lo);
  float w = -log1pf(-u * u);
  float p;
  if (w < 5.0f) {
    w -= 2.5f;
    p = 2.81022636e-08f;
    p = fmaf(p, w, 3.43273939e-07f);
    p = fmaf(p, w, -3.5233877e-06f);
    p = fmaf(p, w, -4.39150654e-06f);
    p = fmaf(p, w, 0.00021858087f);
    p = fmaf(p, w, -0.00125372503f);
    p = fmaf(p, w, -0.00417768164f);
    p = fmaf(p, w, 0.246640727f);
    p = fmaf(p, w, 1.50140941f);
  } else {
    w = sqrtf(w) - 3.0f;
    p = -0.000200214257f;
    p = fmaf(p, w, 0.000100950558f);
    p = fmaf(p, w, 0.00134934322f);
    p = fmaf(p, w, -0.00367342844f);
    p = fmaf(p, w, 0.00573950773f);
    p = fmaf(p, w, -0.0076224613f);
    p = fmaf(p, w, 0.00943887047f);
    p = fmaf(p, w, 1.00167406f);
    p = fmaf(p, w, 2.83297682f);
  }
  return 1.41421356237f * (p * u);
}

__device__ __forceinline__ float wred(float v) {
#pragma unroll
  for (int o = 16; o; o >>= 1) v += __shfl_xor_sync(0xffffffffu, v, o);
  return v;
}

__device__ __forceinline__ void bar_arrive(int k, unsigned long long payload) {
  atomicAdd(&g_sync[k * NSUB + (blockIdx.x & (NSUB - 1))].v, payload + CNT1);
}
__device__ __forceinline__ unsigned long long bar_sweep(int k) {
  unsigned long long s = 0;
#pragma unroll
  for (int i = 0; i < NSUB; ++i)
    s += *((volatile unsigned long long*)&g_sync[k * NSUB + i].v);
  return s;
}
__device__ __forceinline__ unsigned long long bar_wait(int k, unsigned cnt) {
  unsigned long long s;
  do { s = bar_sweep(k); } while ((s >> 52) < (unsigned long long)cnt);
  return s;
}

// ---------------- the one fused kernel ----------------
__global__ void __launch_bounds__(NT, 4) kFused(
    const float* __restrict__ emb, const float* __restrict__ W1,
    const float* __restrict__ b1,  const float* __restrict__ W2,
    const float* __restrict__ b2,  float* __restrict__ out, Keys K) {
  __shared__ __align__(16) float sWT[32 * WSTRIDE];
  __shared__ __align__(16) union {
    float S[2048];
    float W2T[64 * WSTRIDE];
  } U;
  __shared__ __align__(16) float sMT[32 * MSTRIDE];
  __shared__ __align__(16) float sSD[8][64];
  __shared__ __align__(16) float sH[8][32];
  __shared__ float sRed[256];
  __shared__ float sb2s[64];
  __shared__ float swts[32];
  __shared__ float sC[32];

  const int p = blockIdx.x;
  const int tid = threadIdx.x;
  const int lane = tid & 31, w = tid >> 5;
  const int t = p & 127;

  for (int i = tid; i < 2048; i += NT)
    sWT[(i & 31) * WSTRIDE + (i >> 5)] = W1[t * 2048 + i];
  if (tid < 64) sb2s[tid] = b2[tid];
  if (tid < 32) swts[tid] = W1[262144 + tid];

  // ---- P0 + P1 (blocks 0..127; 128-count barrier slot 0) ----
  if (p < 128) {
    {
      const int c = p >> 3, qq = (p & 7) * 256 + tid;
      float s = 0.0f;
#pragma unroll
      for (int r = 0; r < 8; ++r) s += W1[(c * 8 + r) * 2048 + qq];
      __stcg(&g_C[c * 2048 + qq], s);
    }
    __threadfence();
    __syncthreads();
    if (tid == 0) { bar_arrive(0, 0ull); bar_wait(0, 128); }
    __syncthreads();
    __threadfence();

    const int j = p, cj = j >> 3;
    for (int qq = tid; qq < 2048; qq += NT) {
      float s = 0.0f;
      for (int c = cj + 1; c < 16; ++c) s += __ldcg(&g_C[c * 2048 + qq]);
      for (int tt = j + 1; tt < cj * 8 + 8; ++tt) s += W1[tt * 2048 + qq];
      U.S[qq] = s;
    }
    __syncthreads();
    const int o = tid * 4;
    const int b = o >> 5, hh = o & 31;
    float v0 = b1[hh], v1 = b1[hh + 1], v2 = b1[hh + 2], v3 = b1[hh + 3];
    const float* er = emb + b * 8192 + j * 64;
#pragma unroll 8
    for (int d = 0; d < 64; ++d) {
      float ev = er[d];
      const float* spx = &U.S[d * 32 + hh];
      v0 = fmaf(ev, spx[0], v0); v1 = fmaf(ev, spx[1], v1);
      v2 = fmaf(ev, spx[2], v2); v3 = fmaf(ev, spx[3], v3);
    }
    float* pp = &g_pre1[(j * 32 + b) * 32 + hh];
    pp[0] = v0; pp[1] = v1; pp[2] = v2; pp[3] = v3;
    __threadfence();
  }

  // ---- bulk finale sweep (step-independent) ----
  float bulkPart;
  {
    const int base = p * 512 + tid * 2;
    const int bb = base >> 13;
    const int ii = (base >> 6) & 127;
    const int jj = ii >> 2;
    const bool ha = (jj == bb);
    float loc = 0.0f;
    if (!ha) {
      const bool he = ii < 32 * (ii & 3) + bb;
#pragma unroll
      for (int q = 0; q < 2; ++q) {
        const int d = (base & 63) + q;
        const float v = he ? emb[jj * 8192 + ii * 64 + d] : 0.0f;
        out[base + q] = v;
        loc += fabsf(emb[base + q] - v);
      }
    }
    loc = wred(loc);
    if (lane == 0) sRed[w] = loc;
    __syncthreads();
    bulkPart = ((sRed[0] + sRed[1]) + (sRed[2] + sRed[3])) +
               ((sRed[4] + sRed[5]) + (sRed[6] + sRed[7]));
  }
  __syncthreads();

  if (tid == 0)
    bar_arrive(1, (unsigned long long)(bulkPart * 4294967296.0f));

  // overlap barrier 1: W2T load + M_t, c_t precompute
  for (int i = tid; i < 2048; i += NT)
    U.W2T[(i & 63) * WSTRIDE + (i >> 6)] = W2[i];
  __syncthreads();
  for (int idx = tid; idx < 1024; idx += NT) {
    const int h = idx & 31, hh = idx >> 5;
    float acc = 0.f;
#pragma unroll 8
    for (int d = 0; d < 64; ++d)
      acc = fmaf(U.W2T[d * WSTRIDE + hh], sWT[h * WSTRIDE + d], acc);
    sMT[h * MSTRIDE + hh] = acc;
  }
  if (tid < 32) {
    float acc = 0.f;
#pragma unroll 8
    for (int d = 0; d < 64; ++d) acc = fmaf(sb2s[d], sWT[tid * WSTRIDE + d], acc);
    sC[tid] = acc;
  }

  if (tid == 0) {
    unsigned long long v = bar_wait(1, NB);
    sRed[0] = (float)((double)(v & MASK52) * (1.0 / 4294967296.0));
  }
  __syncthreads();
  const float bulkTotal = sRed[0];
  __threadfence();

  // ---- row ownership: n = t + 128*m ----
  const int m = (p >> 7) * 8 + w;
  const int n = t + 128 * m;
  const int b = n & 31;
  const bool sp = (n == 1024 * (b & 3) + 33 * b);
  const bool fg = ((n & 31) == (n >> 7));
  const bool spfg = sp || fg;
  const float sdt = 0.316227766016838f;

  float P = __ldcg(&g_pre1[n * 32 + lane]);
  float a0 = 0.f, a1 = 0.f, err = 0.f;
  const float wt = swts[lane];
  const float b2a = sb2s[lane], b2b = sb2s[32 + lane];
  const float cc = 0.05f * sC[lane];

  const float4* wtRow  = (const float4*)&sWT[lane * WSTRIDE];
  const float4* w2Row0 = (const float4*)&U.W2T[lane * WSTRIDE];
  const float4* w2Row1 = (const float4*)&U.W2T[(32 + lane) * WSTRIDE];
  const float4* mtRow  = (const float4*)&sMT[lane * MSTRIDE];
  const float4* hV     = (const float4*)&sH[w][0];
  const float4* dwV    = (const float4*)&sSD[w][0];

  for (int s = 0; s < NSTEPS; ++s) {
    const float h = fmaxf(P + ((float)s * 0.1f) * wt, 0.0f);
    sH[w][lane] = h;
    __syncwarp();

    // fused pass: score (64 FMA) + u = h.M (32 FMA)
    float p0 = 0.f, q0 = 0.f, p1 = 0.f, q1 = 0.f, u0 = 0.f, u1 = 0.f;
#pragma unroll
    for (int k = 0; k < 8; ++k) {
      const float4 hv = hV[k];
      const float4 wa = w2Row0[k];
      const float4 wb = w2Row1[k];
      const float4 mv = mtRow[k];
      p0 = fmaf(hv.x, wa.x, p0); q0 = fmaf(hv.y, wa.y, q0);
      p0 = fmaf(hv.z, wa.z, p0); q0 = fmaf(hv.w, wa.w, q0);
      p1 = fmaf(hv.x, wb.x, p1); q1 = fmaf(hv.y, wb.y, q1);
      p1 = fmaf(hv.z, wb.z, p1); q1 = fmaf(hv.w, wb.w, q1);
      u0 = fmaf(hv.x, mv.x, u0); u1 = fmaf(hv.y, mv.y, u1);
      u0 = fmaf(hv.z, mv.z, u0); u1 = fmaf(hv.w, mv.w, u1);
    }
    const float s0 = b2a + (p0 + q0);
    const float s1 = b2b + (p1 + q1);
    const float u = u0 + u1;

    // block rowsq partial -> single sync -> tid0 non-blocking arrive
    float rq = wred(fmaf(s0, s0, s1 * s1));
    if (lane == 0) sRed[w] = rq;
    __syncthreads();
    if (tid == 0) {
      float bp = ((sRed[0] + sRed[1]) + (sRed[2] + sRed[3])) +
                 ((sRed[4] + sRed[5]) + (sRed[6] + sRed[7]));
      bar_arrive(2 + s, (unsigned long long)(bp * 4294967296.0f));
    }

    // HEAVY per-warp: threefry noise + v = dW . W1row (overlaps everything)
    const unsigned k0 = K.k0[s], k1 = K.k1[s];
    const float dW0 = bits_to_normal(tfxor(k0, k1, (unsigned)(n * 64 + lane))) * sdt;
    const float dW1 = bits_to_normal(tfxor(k0, k1, (unsigned)(n * 64 + 32 + lane))) * sdt;
    sSD[w][lane] = dW0;
    sSD[w][32 + lane] = dW1;
    __syncwarp();
    float v0 = 0.f, v1 = 0.f, v2 = 0.f, v3 = 0.f;
#pragma unroll
    for (int k = 0; k < 16; ++k) {
      const float4 dv = dwV[k];
      const float4 wv = wtRow[k];
      v0 = fmaf(dv.x, wv.x, v0); v1 = fmaf(dv.y, wv.y, v1);
      v2 = fmaf(dv.z, wv.z, v2); v3 = fmaf(dv.w, wv.w, v3);
    }
    const float vv = (v0 + v1) + (v2 + v3);

    // PER-WARP poll: lane 0 sweeps, shfl-broadcast snorm (no block sync)
    float snorm;
    if (lane == 0) {
      unsigned long long v = bar_wait(2 + s, NB);
      snorm = sqrtf((float)((double)(v & MASK52) * (1.0 / 4294967296.0)));
    }
    snorm = __shfl_sync(0xffffffffu, snorm, 0);

    P += 0.05f * u + cc + snorm * vv;
    if (spfg) {
      a0 += 0.05f * s0 + snorm * dW0;
      a1 += 0.05f * s1 + snorm * dW1;
      if (sp) {
        float sq = wred(fmaf(a0, a0, a1 * a1));
        if (lane == 0) err += sq * (1.0f / 64.0f);
      }
    }
  }

  // ---- tail ----
  if (sp && lane == 0) __stcg(&g_err32[b], err);
  if (fg) {
    const int i = n >> 5;
    const int bb2 = i >> 2;
    const bool he2 = i < 32 * (i & 3) + bb2;
    const int e0 = bb2 * 8192 + i * 64 + lane;
    const float em0 = emb[e0], em1 = emb[e0 + 32];
    const float o0 = (he2 ? em0 : 0.0f) + a0;
    const float o1 = (he2 ? em1 : 0.0f) + a1;
    out[e0] = o0;
    out[e0 + 32] = o1;
    float part = wred(fabsf(em0 - o0) + fabsf(em1 - o1));
    if (lane == 0) __stcg(&g_fgabs[i], part);
  }
  __threadfence();
  __syncthreads();
  if (tid == 0) bar_arrive(12, 0ull);

  // block 0: poll final barrier, zero ALL sync state (replay-safe), scalars
  if (p == 0) {
    if (tid == 0) bar_wait(12, NB);
    __syncthreads();
    for (int i = tid; i < NBAR * NSUB; i += NT)
      *((volatile unsigned long long*)&g_sync[i].v) = 0ull;
    if (tid < 32) {
      float e = __ldcg(&g_err32[tid]);
      float f = __ldcg(&g_fgabs[tid]) + __ldcg(&g_fgabs[tid + 32]) +
                __ldcg(&g_fgabs[tid + 64]) + __ldcg(&g_fgabs[tid + 96]);
      float se = wred(e);
      float sf = wred(f);
      if (tid == 0) {
        out[NELEMS] = se;                                         // step_loss
        out[NELEMS + 1] = (bulkTotal + sf) * (1.0f / 262144.0f);  // sequence_loss
      }
    }
  }
}

// ---------------- launch ----------------
extern "C" void kernel_launch(void* const* d_in, const int* in_sizes, int n_in,
                              void* d_out, int out_size) {
  const float* emb = (const float*)d_in[0];
  const float* W1  = (const float*)d_in[1];
  const float* b1  = (const float*)d_in[2];
  const float* W2  = (const float*)d_in[3];
  const float* b2  = (const float*)d_in[4];
  float* out = (float*)d_out;

  Keys K;
  for (int i = 0; i < NSTEPS; ++i)
    tf2x32_host(0u, 42u, 0u, (unsigned)i, &K.k0[i], &K.k1[i]);

  kFused<<<NB, NT>>>(emb, W1, b1, W2, b2, out, K);
}

// round 15
// speedup vs baseline: 1.5496x; 1.5496x over previous
#include <cuda_runtime.h>
#include <cstdint>

#define NSTEPS 10
#define NB     512
#define NT     256
#define NBAR   13
#define NSUB   16
#define NELEMS 262144
#define MASK52 ((1ull << 52) - 1ull)
#define CNT1   (1ull << 52)
#define WSTRIDE 76

// ---------------- device scratch ----------------
__device__ float g_C[16 * 2048];
__device__ float g_pre1[4096 * 32];
__device__ float g_err32[32];
__device__ float g_fgabs[128];
struct SSlot { unsigned long long v; unsigned long long pad[31]; };  // 256B
__device__ SSlot g_sync[NBAR * NSUB];   // zero-init; block 0 re-zeroes at run end

struct Keys { unsigned k0[NSTEPS]; unsigned k1[NSTEPS]; };

// ---------------- threefry2x32 ----------------
#define TF_ROT_H(x, r) (((x) << (r)) | ((x) >> (32 - (r))))
static inline void tf2x32_host(unsigned k0, unsigned k1, unsigned x0, unsigned x1,
                               unsigned* o0, unsigned* o1) {
  unsigned ks0 = k0, ks1 = k1, ks2 = k0 ^ k1 ^ 0x1BD11BDAu;
  x0 += ks0; x1 += ks1;
#define TF_R4(a,b,c,d) \
  x0 += x1; x1 = TF_ROT_H(x1,a); x1 ^= x0; \
  x0 += x1; x1 = TF_ROT_H(x1,b); x1 ^= x0; \
  x0 += x1; x1 = TF_ROT_H(x1,c); x1 ^= x0; \
  x0 += x1; x1 = TF_ROT_H(x1,d); x1 ^= x0;
  TF_R4(13,15,26,6)  x0 += ks1; x1 += ks2 + 1u;
  TF_R4(17,29,16,24) x0 += ks2; x1 += ks0 + 2u;
  TF_R4(13,15,26,6)  x0 += ks0; x1 += ks1 + 3u;
  TF_R4(17,29,16,24) x0 += ks1; x1 += ks2 + 4u;
  TF_R4(13,15,26,6)  x0 += ks2; x1 += ks0 + 5u;
#undef TF_R4
  *o0 = x0; *o1 = x1;
}

// device: single-instruction SHF rotates
__device__ __forceinline__ unsigned rotl(unsigned x, int r) {
  return __funnelshift_l(x, x, r);
}
__device__ __forceinline__ unsigned tfxor(unsigned k0, unsigned k1, unsigned e) {
  unsigned ks2 = k0 ^ k1 ^ 0x1BD11BDAu;
  unsigned x0 = k0;        // 0 + ks0
  unsigned x1 = e + k1;    // e + ks1
#define TF_R4D(a,b,c,d) \
  x0 += x1; x1 = rotl(x1,a); x1 ^= x0; \
  x0 += x1; x1 = rotl(x1,b); x1 ^= x0; \
  x0 += x1; x1 = rotl(x1,c); x1 ^= x0; \
  x0 += x1; x1 = rotl(x1,d); x1 ^= x0;
  TF_R4D(13,15,26,6)  x0 += k1;  x1 += ks2 + 1u;
  TF_R4D(17,29,16,24) x0 += ks2; x1 += k0 + 2u;
  TF_R4D(13,15,26,6)  x0 += k0;  x1 += k1 + 3u;
  TF_R4D(17,29,16,24) x0 += k1;  x1 += ks2 + 4u;
  TF_R4D(13,15,26,6)  x0 += ks2; x1 += k0 + 5u;
#undef TF_R4D
  return x0 ^ x1;
}

__device__ __forceinline__ float bits_to_normal(unsigned bits) {
  float f = __uint_as_float((bits >> 9) | 0x3f800000u) - 1.0f;
  const float lo = __uint_as_float(0xBF7FFFFFu);
  float u = fmaxf(lo, f * 2.0f + lo);
  float w = -log1pf(-u * u);
  float p;
  if (w < 5.0f) {
    w -= 2.5f;
    p = 2.81022636e-08f;
    p = fmaf(p, w, 3.43273939e-07f);
    p = fmaf(p, w, -3.5233877e-06f);
    p = fmaf(p, w, -4.39150654e-06f);
    p = fmaf(p, w, 0.00021858087f);
    p = fmaf(p, w, -0.00125372503f);
    p = fmaf(p, w, -0.00417768164f);
    p = fmaf(p, w, 0.246640727f);
    p = fmaf(p, w, 1.50140941f);
  } else {
    w = sqrtf(w) - 3.0f;
    p = -0.000200214257f;
    p = fmaf(p, w, 0.000100950558f);
    p = fmaf(p, w, 0.00134934322f);
    p = fmaf(p, w, -0.00367342844f);
    p = fmaf(p, w, 0.00573950773f);
    p = fmaf(p, w, -0.0076224613f);
    p = fmaf(p, w, 0.00943887047f);
    p = fmaf(p, w, 1.00167406f);
    p = fmaf(p, w, 2.83297682f);
  }
  return 1.41421356237f * (p * u);
}

__device__ __forceinline__ float wred(float v) {
#pragma unroll
  for (int o = 16; o; o >>= 1) v += __shfl_xor_sync(0xffffffffu, v, o);
  return v;
}

__device__ __forceinline__ void bar_arrive(int k, unsigned long long payload) {
  atomicAdd(&g_sync[k * NSUB + (blockIdx.x & (NSUB - 1))].v, payload + CNT1);
}
__device__ __forceinline__ unsigned long long bar_sweep(int k) {
  unsigned long long s = 0;
#pragma unroll
  for (int i = 0; i < NSUB; ++i)
    s += *((volatile unsigned long long*)&g_sync[k * NSUB + i].v);
  return s;
}
__device__ __forceinline__ unsigned long long bar_wait(int k, unsigned cnt) {
  unsigned long long s;
  do { s = bar_sweep(k); } while ((s >> 52) < (unsigned long long)cnt);
  return s;
}

// ---------------- the one fused kernel ----------------
__global__ void __launch_bounds__(NT, 4) kFused(
    const float* __restrict__ emb, const float* __restrict__ W1,
    const float* __restrict__ b1,  const float* __restrict__ W2,
    const float* __restrict__ b2,  float* __restrict__ out, Keys K) {
  __shared__ __align__(16) float sWT[32 * WSTRIDE];   // W1_t transposed [h][d]
  __shared__ __align__(16) union {
    float S[2048];
    float W2T[64 * WSTRIDE];                          // [c][hh]
  } U;
  __shared__ __align__(16) float sAcc[8][64];         // per-warp acc staging
  __shared__ __align__(16) float sH[8][32];
  __shared__ float sRed[256];
  __shared__ float sb2s[64];
  __shared__ float swts[32];

  const int p = blockIdx.x;
  const int tid = threadIdx.x;
  const int lane = tid & 31, w = tid >> 5;
  const int t = p & 127;

  for (int i = tid; i < 2048; i += NT)
    sWT[(i & 31) * WSTRIDE + (i >> 5)] = W1[t * 2048 + i];
  if (tid < 64) sb2s[tid] = b2[tid];
  if (tid < 32) swts[tid] = W1[262144 + tid];

  // ---- P0 + P1 (blocks 0..127; 128-count barrier slot 0) ----
  if (p < 128) {
    {
      const int c = p >> 3, qq = (p & 7) * 256 + tid;
      float s = 0.0f;
#pragma unroll
      for (int r = 0; r < 8; ++r) s += W1[(c * 8 + r) * 2048 + qq];
      __stcg(&g_C[c * 2048 + qq], s);
    }
    __threadfence();
    __syncthreads();
    if (tid == 0) { bar_arrive(0, 0ull); bar_wait(0, 128); }
    __syncthreads();
    __threadfence();

    const int j = p, cj = j >> 3;
    for (int qq = tid; qq < 2048; qq += NT) {
      float s = 0.0f;
      for (int c = cj + 1; c < 16; ++c) s += __ldcg(&g_C[c * 2048 + qq]);
      for (int tt = j + 1; tt < cj * 8 + 8; ++tt) s += W1[tt * 2048 + qq];
      U.S[qq] = s;
    }
    __syncthreads();
    const int o = tid * 4;
    const int b = o >> 5, hh = o & 31;
    float v0 = b1[hh], v1 = b1[hh + 1], v2 = b1[hh + 2], v3 = b1[hh + 3];
    const float* er = emb + b * 8192 + j * 64;
#pragma unroll 8
    for (int d = 0; d < 64; ++d) {
      float ev = er[d];
      const float* spx = &U.S[d * 32 + hh];
      v0 = fmaf(ev, spx[0], v0); v1 = fmaf(ev, spx[1], v1);
      v2 = fmaf(ev, spx[2], v2); v3 = fmaf(ev, spx[3], v3);
    }
    float* pp = &g_pre1[(j * 32 + b) * 32 + hh];
    pp[0] = v0; pp[1] = v1; pp[2] = v2; pp[3] = v3;
    __threadfence();
  }

  // ---- bulk finale sweep (step-independent) ----
  float bulkPart;
  {
    const int base = p * 512 + tid * 2;
    const int bb = base >> 13;
    const int ii = (base >> 6) & 127;
    const int jj = ii >> 2;
    const bool ha = (jj == bb);
    float loc = 0.0f;
    if (!ha) {
      const bool he = ii < 32 * (ii & 3) + bb;
#pragma unroll
      for (int q = 0; q < 2; ++q) {
        const int d = (base & 63) + q;
        const float v = he ? emb[jj * 8192 + ii * 64 + d] : 0.0f;
        out[base + q] = v;
        loc += fabsf(emb[base + q] - v);
      }
    }
    loc = wred(loc);
    if (lane == 0) sRed[w] = loc;
    __syncthreads();
    bulkPart = ((sRed[0] + sRed[1]) + (sRed[2] + sRed[3])) +
               ((sRed[4] + sRed[5]) + (sRed[6] + sRed[7]));
  }
  __syncthreads();

  if (tid == 0)
    bar_arrive(1, (unsigned long long)(bulkPart * 4294967296.0f));

  // overlap barrier 1: W2T load
  for (int i = tid; i < 2048; i += NT)
    U.W2T[(i & 63) * WSTRIDE + (i >> 6)] = W2[i];
  __syncthreads();

  if (tid == 0) {
    unsigned long long v = bar_wait(1, NB);
    sRed[0] = (float)((double)(v & MASK52) * (1.0 / 4294967296.0));
  }
  __syncthreads();
  const float bulkTotal = sRed[0];
  __threadfence();

  // ---- row ownership: n = t + 128*m ----
  const int m = (p >> 7) * 8 + w;
  const int n = t + 128 * m;
  const int b = n & 31;
  const bool sp = (n == 1024 * (b & 3) + 33 * b);
  const bool fg = ((n & 31) == (n >> 7));
  const float sdt = 0.316227766016838f;

  const float pre = __ldcg(&g_pre1[n * 32 + lane]);
  float a0 = 0.f, a1 = 0.f, err = 0.f;
  const float wt = swts[lane];
  const float b2a = sb2s[lane], b2b = sb2s[32 + lane];

  const float4* wtRow  = (const float4*)&sWT[lane * WSTRIDE];
  const float4* w2Row0 = (const float4*)&U.W2T[lane * WSTRIDE];
  const float4* w2Row1 = (const float4*)&U.W2T[(32 + lane) * WSTRIDE];
  const float4* accV   = (const float4*)&sAcc[w][0];
  const float4* hV     = (const float4*)&sH[w][0];

  for (int s = 0; s < NSTEPS; ++s) {
    // stage acc; direct hidden matvec (96 instr)
    sAcc[w][lane] = a0;
    sAcc[w][32 + lane] = a1;
    __syncwarp();
    float x0 = 0.f, x1 = 0.f, x2 = 0.f, x3 = 0.f;
#pragma unroll
    for (int k = 0; k < 16; ++k) {
      const float4 av = accV[k];
      const float4 wv = wtRow[k];
      x0 = fmaf(av.x, wv.x, x0);
      x1 = fmaf(av.y, wv.y, x1);
      x2 = fmaf(av.z, wv.z, x2);
      x3 = fmaf(av.w, wv.w, x3);
    }
    const float h = fmaxf(pre + ((float)s * 0.1f) * wt + ((x0 + x1) + (x2 + x3)), 0.0f);
    sH[w][lane] = h;
    __syncwarp();

    // score (152 instr)
    float p0 = 0.f, q0 = 0.f, p1 = 0.f, q1 = 0.f;
#pragma unroll
    for (int k = 0; k < 8; ++k) {
      const float4 hv = hV[k];
      const float4 wa = w2Row0[k];
      const float4 wb = w2Row1[k];
      p0 = fmaf(hv.x, wa.x, p0); q0 = fmaf(hv.y, wa.y, q0);
      p0 = fmaf(hv.z, wa.z, p0); q0 = fmaf(hv.w, wa.w, q0);
      p1 = fmaf(hv.x, wb.x, p1); q1 = fmaf(hv.y, wb.y, q1);
      p1 = fmaf(hv.z, wb.z, p1); q1 = fmaf(hv.w, wb.w, q1);
    }
    const float s0 = b2a + (p0 + q0);
    const float s1 = b2b + (p1 + q1);

    // rowsq -> single sync -> tid0 non-blocking arrive
    float rq = wred(fmaf(s0, s0, s1 * s1));
    if (lane == 0) sRed[w] = rq;
    __syncthreads();
    if (tid == 0) {
      float bp = ((sRed[0] + sRed[1]) + (sRed[2] + sRed[3])) +
                 ((sRed[4] + sRed[5]) + (sRed[6] + sRed[7]));
      bar_arrive(2 + s, (unsigned long long)(bp * 4294967296.0f));
    }

    // noise overlaps the barrier window
    const unsigned k0 = K.k0[s], k1 = K.k1[s];
    const float dW0 = bits_to_normal(tfxor(k0, k1, (unsigned)(n * 64 + lane))) * sdt;
    const float dW1 = bits_to_normal(tfxor(k0, k1, (unsigned)(n * 64 + 32 + lane))) * sdt;

    // tid0 polls, broadcast snorm
    if (tid == 0) {
      unsigned long long v = bar_wait(2 + s, NB);
      sRed[0] = (float)((double)(v & MASK52) * (1.0 / 4294967296.0));
    }
    __syncthreads();
    const float snorm = sqrtf(sRed[0]);

    a0 += 0.05f * s0 + snorm * dW0;
    a1 += 0.05f * s1 + snorm * dW1;

    if (sp) {
      float sq = wred(fmaf(a0, a0, a1 * a1));
      if (lane == 0) err += sq * (1.0f / 64.0f);
    }
  }

  // ---- tail ----
  if (sp && lane == 0) __stcg(&g_err32[b], err);
  if (fg) {
    const int i = n >> 5;
    const int bb2 = i >> 2;
    const bool he2 = i < 32 * (i & 3) + bb2;
    const int e0 = bb2 * 8192 + i * 64 + lane;
    const float em0 = emb[e0], em1 = emb[e0 + 32];
    const float o0 = (he2 ? em0 : 0.0f) + a0;
    const float o1 = (he2 ? em1 : 0.0f) + a1;
    out[e0] = o0;
    out[e0 + 32] = o1;
    float part = wred(fabsf(em0 - o0) + fabsf(em1 - o1));
    if (lane == 0) __stcg(&g_fgabs[i], part);
  }
  __threadfence();
  __syncthreads();
  if (tid == 0) bar_arrive(12, 0ull);

  // block 0: poll final barrier, zero ALL sync state (replay-safe), scalars
  if (p == 0) {
    if (tid == 0) bar_wait(12, NB);
    __syncthreads();
    for (int i = tid; i < NBAR * NSUB; i += NT)
      *((volatile unsigned long long*)&g_sync[i].v) = 0ull;
    if (tid < 32) {
      float e = __ldcg(&g_err32[tid]);
      float f = __ldcg(&g_fgabs[tid]) + __ldcg(&g_fgabs[tid + 32]) +
                __ldcg(&g_fgabs[tid + 64]) + __ldcg(&g_fgabs[tid + 96]);
      float se = wred(e);
      float sf = wred(f);
      if (tid == 0) {
        out[NELEMS] = se;                                         // step_loss
        out[NELEMS + 1] = (bulkTotal + sf) * (1.0f / 262144.0f);  // sequence_loss
      }
    }
  }
}

// ---------------- launch ----------------
extern "C" void kernel_launch(void* const* d_in, const int* in_sizes, int n_in,
                              void* d_out, int out_size) {
  const float* emb = (const float*)d_in[0];
  const float* W1  = (const float*)d_in[1];
  const float* b1  = (const float*)d_in[2];
  const float* W2  = (const float*)d_in[3];
  const float* b2  = (const float*)d_in[4];
  float* out = (float*)d_out;

  Keys K;
  for (int i = 0; i < NSTEPS; ++i)
    tf2x32_host(0u, 42u, 0u, (unsigned)i, &K.k0[i], &K.k1[i]);

  kFused<<<NB, NT>>>(emb, W1, b1, W2, b2, out, K);
}

// round 16
// speedup vs baseline: 1.6251x; 1.0487x over previous
#include <cuda_runtime.h>
#include <cstdint>

#define NSTEPS 10
#define NB     512
#define NT     256
#define NBAR   13
#define NSUB   16
#define NELEMS 262144
#define MASK52 ((1ull << 52) - 1ull)
#define CNT1   (1ull << 52)
#define WSTRIDE 76

// ---------------- device scratch ----------------
__device__ float g_C[16 * 2048];
__device__ float g_pre1[4096 * 32];
__device__ float g_err32[32];
__device__ float g_fgabs[128];
struct SSlot { unsigned long long v; unsigned long long pad[31]; };  // 256B
__device__ SSlot g_sync[NBAR * NSUB];   // zero-init; block 0 re-zeroes at run end

struct Keys { unsigned k0[NSTEPS]; unsigned k1[NSTEPS]; };

// ---------------- threefry2x32 ----------------
#define TF_ROT_H(x, r) (((x) << (r)) | ((x) >> (32 - (r))))
static inline void tf2x32_host(unsigned k0, unsigned k1, unsigned x0, unsigned x1,
                               unsigned* o0, unsigned* o1) {
  unsigned ks0 = k0, ks1 = k1, ks2 = k0 ^ k1 ^ 0x1BD11BDAu;
  x0 += ks0; x1 += ks1;
#define TF_R4(a,b,c,d) \
  x0 += x1; x1 = TF_ROT_H(x1,a); x1 ^= x0; \
  x0 += x1; x1 = TF_ROT_H(x1,b); x1 ^= x0; \
  x0 += x1; x1 = TF_ROT_H(x1,c); x1 ^= x0; \
  x0 += x1; x1 = TF_ROT_H(x1,d); x1 ^= x0;
  TF_R4(13,15,26,6)  x0 += ks1; x1 += ks2 + 1u;
  TF_R4(17,29,16,24) x0 += ks2; x1 += ks0 + 2u;
  TF_R4(13,15,26,6)  x0 += ks0; x1 += ks1 + 3u;
  TF_R4(17,29,16,24) x0 += ks1; x1 += ks2 + 4u;
  TF_R4(13,15,26,6)  x0 += ks2; x1 += ks0 + 5u;
#undef TF_R4
  *o0 = x0; *o1 = x1;
}

__device__ __forceinline__ unsigned rotl(unsigned x, int r) {
  return __funnelshift_l(x, x, r);
}
__device__ __forceinline__ unsigned tfxor(unsigned k0, unsigned k1, unsigned e) {
  unsigned ks2 = k0 ^ k1 ^ 0x1BD11BDAu;
  unsigned x0 = k0;        // 0 + ks0
  unsigned x1 = e + k1;    // e + ks1
#define TF_R4D(a,b,c,d) \
  x0 += x1; x1 = rotl(x1,a); x1 ^= x0; \
  x0 += x1; x1 = rotl(x1,b); x1 ^= x0; \
  x0 += x1; x1 = rotl(x1,c); x1 ^= x0; \
  x0 += x1; x1 = rotl(x1,d); x1 ^= x0;
  TF_R4D(13,15,26,6)  x0 += k1;  x1 += ks2 + 1u;
  TF_R4D(17,29,16,24) x0 += ks2; x1 += k0 + 2u;
  TF_R4D(13,15,26,6)  x0 += k0;  x1 += k1 + 3u;
  TF_R4D(17,29,16,24) x0 += k1;  x1 += ks2 + 4u;
  TF_R4D(13,15,26,6)  x0 += ks2; x1 += k0 + 5u;
#undef TF_R4D
  return x0 ^ x1;
}

__device__ __forceinline__ float bits_to_normal(unsigned bits) {
  float f = __uint_as_float((bits >> 9) | 0x3f800000u) - 1.0f;
  const float lo = __uint_as_float(0xBF7FFFFFu);
  float u = fmaxf(lo, f * 2.0f + lo);
  float w = -log1pf(-u * u);
  float p;
  if (w < 5.0f) {
    w -= 2.5f;
    p = 2.81022636e-08f;
    p = fmaf(p, w, 3.43273939e-07f);
    p = fmaf(p, w, -3.5233877e-06f);
    p = fmaf(p, w, -4.39150654e-06f);
    p = fmaf(p, w, 0.00021858087f);
    p = fmaf(p, w, -0.00125372503f);
    p = fmaf(p, w, -0.00417768164f);
    p = fmaf(p, w, 0.246640727f);
    p = fmaf(p, w, 1.50140941f);
  } else {
    w = sqrtf(w) - 3.0f;
    p = -0.000200214257f;
    p = fmaf(p, w, 0.000100950558f);
    p = fmaf(p, w, 0.00134934322f);
    p = fmaf(p, w, -0.00367342844f);
    p = fmaf(p, w, 0.00573950773f);
    p = fmaf(p, w, -0.0076224613f);
    p = fmaf(p, w, 0.00943887047f);
    p = fmaf(p, w, 1.00167406f);
    p = fmaf(p, w, 2.83297682f);
  }
  return 1.41421356237f * (p * u);
}

__device__ __forceinline__ float wred(float v) {
#pragma unroll
  for (int o = 16; o; o >>= 1) v += __shfl_xor_sync(0xffffffffu, v, o);
  return v;
}

__device__ __forceinline__ void bar_arrive(int k, unsigned long long payload) {
  atomicAdd(&g_sync[k * NSUB + (blockIdx.x & (NSUB - 1))].v, payload + CNT1);
}
// ldcg sweeps (L2-coherent, no strong-load serialization against the atomics)
__device__ __forceinline__ unsigned long long bar_sweep(int k) {
  unsigned long long s = 0;
#pragma unroll
  for (int i = 0; i < NSUB; ++i)
    s += __ldcg(&g_sync[k * NSUB + i].v);
  return s;
}
__device__ __forceinline__ unsigned long long bar_wait(int k, unsigned cnt) {
  unsigned long long s = bar_sweep(k);
  while ((s >> 52) < (unsigned long long)cnt) {
    __nanosleep(64);
    s = bar_sweep(k);
  }
  return s;
}

// ---------------- the one fused kernel ----------------
__global__ void __launch_bounds__(NT, 4) kFused(
    const float* __restrict__ emb, const float* __restrict__ W1,
    const float* __restrict__ b1,  const float* __restrict__ W2,
    const float* __restrict__ b2,  float* __restrict__ out, Keys K) {
  __shared__ __align__(16) float sWT[32 * WSTRIDE];   // W1_t transposed [h][d]
  __shared__ __align__(16) union {
    float S[2048];
    float W2T[64 * WSTRIDE];                          // [c][hh]
  } U;
  __shared__ __align__(16) float sSD[8][128];         // per-warp: score[0:64], dW[64:128]
  __shared__ __align__(16) float sH[8][32];
  __shared__ float sRed[256];
  __shared__ float sb2s[64];
  __shared__ float swts[32];

  const int p = blockIdx.x;
  const int tid = threadIdx.x;
  const int lane = tid & 31, w = tid >> 5;
  const int t = p & 127;

  for (int i = tid; i < 2048; i += NT)
    sWT[(i & 31) * WSTRIDE + (i >> 5)] = W1[t * 2048 + i];
  if (tid < 64) sb2s[tid] = b2[tid];
  if (tid < 32) swts[tid] = W1[262144 + tid];

  // ---- P0 + P1 (blocks 0..127; 128-count barrier slot 0) ----
  if (p < 128) {
    {
      const int c = p >> 3, qq = (p & 7) * 256 + tid;
      float s = 0.0f;
#pragma unroll
      for (int r = 0; r < 8; ++r) s += W1[(c * 8 + r) * 2048 + qq];
      __stcg(&g_C[c * 2048 + qq], s);
    }
    __threadfence();
    __syncthreads();
    if (tid == 0) { bar_arrive(0, 0ull); bar_wait(0, 128); }
    __syncthreads();
    __threadfence();

    const int j = p, cj = j >> 3;
    for (int qq = tid; qq < 2048; qq += NT) {
      float s = 0.0f;
      for (int c = cj + 1; c < 16; ++c) s += __ldcg(&g_C[c * 2048 + qq]);
      for (int tt = j + 1; tt < cj * 8 + 8; ++tt) s += W1[tt * 2048 + qq];
      U.S[qq] = s;
    }
    __syncthreads();
    const int o = tid * 4;
    const int b = o >> 5, hh = o & 31;
    float v0 = b1[hh], v1 = b1[hh + 1], v2 = b1[hh + 2], v3 = b1[hh + 3];
    const float* er = emb + b * 8192 + j * 64;
#pragma unroll 8
    for (int d = 0; d < 64; ++d) {
      float ev = er[d];
      const float* spx = &U.S[d * 32 + hh];
      v0 = fmaf(ev, spx[0], v0); v1 = fmaf(ev, spx[1], v1);
      v2 = fmaf(ev, spx[2], v2); v3 = fmaf(ev, spx[3], v3);
    }
    float* pp = &g_pre1[(j * 32 + b) * 32 + hh];
    pp[0] = v0; pp[1] = v1; pp[2] = v2; pp[3] = v3;
    __threadfence();
  }

  // ---- bulk finale sweep (step-independent) ----
  float bulkPart;
  {
    const int base = p * 512 + tid * 2;
    const int bb = base >> 13;
    const int ii = (base >> 6) & 127;
    const int jj = ii >> 2;
    const bool ha = (jj == bb);
    float loc = 0.0f;
    if (!ha) {
      const bool he = ii < 32 * (ii & 3) + bb;
#pragma unroll
      for (int q = 0; q < 2; ++q) {
        const int d = (base & 63) + q;
        const float v = he ? emb[jj * 8192 + ii * 64 + d] : 0.0f;
        out[base + q] = v;
        loc += fabsf(emb[base + q] - v);
      }
    }
    loc = wred(loc);
    if (lane == 0) sRed[w] = loc;
    __syncthreads();
    bulkPart = ((sRed[0] + sRed[1]) + (sRed[2] + sRed[3])) +
               ((sRed[4] + sRed[5]) + (sRed[6] + sRed[7]));
  }
  __syncthreads();

  if (tid == 0)
    bar_arrive(1, (unsigned long long)(bulkPart * 4294967296.0f));

  // overlap barrier 1: W2T transposed load
  for (int i = tid; i < 2048; i += NT)
    U.W2T[(i & 63) * WSTRIDE + (i >> 6)] = W2[i];
  __syncthreads();

  if (tid == 0) {
    unsigned long long v = bar_wait(1, NB);
    sRed[0] = (float)((double)(v & MASK52) * (1.0 / 4294967296.0));
  }
  __syncthreads();
  const float bulkTotal = sRed[0];
  __threadfence();

  // ---- row ownership: n = t + 128*m ----
  const int m = (p >> 7) * 8 + w;
  const int n = t + 128 * m;
  const int b = n & 31;
  const bool sp = (n == 1024 * (b & 3) + 33 * b);
  const bool fg = ((n & 31) == (n >> 7));
  const bool spfg = sp || fg;
  const float sdt = 0.316227766016838f;

  float P = __ldcg(&g_pre1[n * 32 + lane]);   // running pre-activation
  float a0 = 0.f, a1 = 0.f, err = 0.f;
  const float wt = swts[lane];
  const float b2a = sb2s[lane], b2b = sb2s[32 + lane];

  const float4* wtRow  = (const float4*)&sWT[lane * WSTRIDE];
  const float4* w2Row0 = (const float4*)&U.W2T[lane * WSTRIDE];
  const float4* w2Row1 = (const float4*)&U.W2T[(32 + lane) * WSTRIDE];
  const float4* scV = (const float4*)&sSD[w][0];
  const float4* dwV = (const float4*)&sSD[w][64];
  const float4* hV  = (const float4*)&sH[w][0];

  for (int s = 0; s < NSTEPS; ++s) {
    // LIGHT: hidden from running P (no matvec)
    const float h = fmaxf(P + ((float)s * 0.1f) * wt, 0.0f);
    sH[w][lane] = h;
    __syncwarp();

    // LIGHT: score matvec only
    float p0 = 0.f, q0 = 0.f, p1 = 0.f, q1 = 0.f;
#pragma unroll
    for (int k = 0; k < 8; ++k) {
      const float4 hv = hV[k];
      const float4 wa = w2Row0[k];
      const float4 wb = w2Row1[k];
      p0 = fmaf(hv.x, wa.x, p0); q0 = fmaf(hv.y, wa.y, q0);
      p0 = fmaf(hv.z, wa.z, p0); q0 = fmaf(hv.w, wa.w, q0);
      p1 = fmaf(hv.x, wb.x, p1); q1 = fmaf(hv.y, wb.y, q1);
      p1 = fmaf(hv.z, wb.z, p1); q1 = fmaf(hv.w, wb.w, q1);
    }
    const float s0 = b2a + (p0 + q0);
    const float s1 = b2b + (p1 + q1);

    // rowsq -> single sync -> tid0 non-blocking arrive
    float rq = wred(fmaf(s0, s0, s1 * s1));
    if (lane == 0) sRed[w] = rq;
    __syncthreads();
    if (tid == 0) {
      float bp = ((sRed[0] + sRed[1]) + (sRed[2] + sRed[3])) +
                 ((sRed[4] + sRed[5]) + (sRed[6] + sRed[7]));
      bar_arrive(2 + s, (unsigned long long)(bp * 4294967296.0f));
    }

    // HEAVY (overlaps barrier): threefry noise
    const unsigned k0 = K.k0[s], k1 = K.k1[s];
    const float dW0 = bits_to_normal(tfxor(k0, k1, (unsigned)(n * 64 + lane))) * sdt;
    const float dW1 = bits_to_normal(tfxor(k0, k1, (unsigned)(n * 64 + 32 + lane))) * sdt;
    sSD[w][lane] = s0;       sSD[w][32 + lane] = s1;
    sSD[w][64 + lane] = dW0; sSD[w][96 + lane] = dW1;
    __syncwarp();

    // HEAVY: fused dual matvec u = score.W1row, v = dW.W1row
    float u0 = 0.f, u1 = 0.f, v0 = 0.f, v1 = 0.f;
#pragma unroll
    for (int k = 0; k < 16; ++k) {
      const float4 wv = wtRow[k];
      const float4 sc = scV[k];
      const float4 dv = dwV[k];
      u0 = fmaf(sc.x, wv.x, u0); u1 = fmaf(sc.y, wv.y, u1);
      u0 = fmaf(sc.z, wv.z, u0); u1 = fmaf(sc.w, wv.w, u1);
      v0 = fmaf(dv.x, wv.x, v0); v1 = fmaf(dv.y, wv.y, v1);
      v0 = fmaf(dv.z, wv.z, v0); v1 = fmaf(dv.w, wv.w, v1);
    }
    const float uu = u0 + u1, vv = v0 + v1;

    // tid0 polls (with backoff), broadcast snorm
    if (tid == 0) {
      unsigned long long v = bar_wait(2 + s, NB);
      sRed[0] = (float)((double)(v & MASK52) * (1.0 / 4294967296.0));
    }
    __syncthreads();
    const float snorm = sqrtf(sRed[0]);

    // LIGHT: state update
    P += 0.05f * uu + snorm * vv;
    if (spfg) {
      a0 += 0.05f * s0 + snorm * dW0;
      a1 += 0.05f * s1 + snorm * dW1;
      if (sp) {
        float sq = wred(fmaf(a0, a0, a1 * a1));
        if (lane == 0) err += sq * (1.0f / 64.0f);
      }
    }
  }

  // ---- tail ----
  if (sp && lane == 0) __stcg(&g_err32[b], err);
  if (fg) {
    const int i = n >> 5;
    const int bb2 = i >> 2;
    const bool he2 = i < 32 * (i & 3) + bb2;
    const int e0 = bb2 * 8192 + i * 64 + lane;
    const float em0 = emb[e0], em1 = emb[e0 + 32];
    const float o0 = (he2 ? em0 : 0.0f) + a0;
    const float o1 = (he2 ? em1 : 0.0f) + a1;
    out[e0] = o0;
    out[e0 + 32] = o1;
    float part = wred(fabsf(em0 - o0) + fabsf(em1 - o1));
    if (lane == 0) __stcg(&g_fgabs[i], part);
  }
  __threadfence();
  __syncthreads();
  if (tid == 0) bar_arrive(12, 0ull);

  // block 0: poll final barrier, zero ALL sync state (replay-safe), scalars
  if (p == 0) {
    if (tid == 0) bar_wait(12, NB);
    __syncthreads();
    for (int i = tid; i < NBAR * NSUB; i += NT)
      *((volatile unsigned long long*)&g_sync[i].v) = 0ull;
    if (tid < 32) {
      float e = __ldcg(&g_err32[tid]);
      float f = __ldcg(&g_fgabs[tid]) + __ldcg(&g_fgabs[tid + 32]) +
                __ldcg(&g_fgabs[tid + 64]) + __ldcg(&g_fgabs[tid + 96]);
      float se = wred(e);
      float sf = wred(f);
      if (tid == 0) {
        out[NELEMS] = se;                                         // step_loss
        out[NELEMS + 1] = (bulkTotal + sf) * (1.0f / 262144.0f);  // sequence_loss
      }
    }
  }
}

// ---------------- launch ----------------
extern "C" void kernel_launch(void* const* d_in, const int* in_sizes, int n_in,
                              void* d_out, int out_size) {
  const float* emb = (const float*)d_in[0];
  const float* W1  = (const float*)d_in[1];
  const float* b1  = (const float*)d_in[2];
  const float* W2  = (const float*)d_in[3];
  const float* b2  = (const float*)d_in[4];
  float* out = (float*)d_out;

  Keys K;
  for (int i = 0; i < NSTEPS; ++i)
    tf2x32_host(0u, 42u, 0u, (unsigned)i, &K.k0[i], &K.k1[i]);

  kFused<<<NB, NT>>>(emb, W1, b1, W2, b2, out, K);
}